// round 1
// baseline (speedup 1.0000x reference)
#include <cuda_runtime.h>

// ---------------------------------------------------------------------------
// Upsampling: out = lrelu( [x_up, lrelu(gather(x_down) @ W_lin + b_lin)] @ W_fus + b_fus )
//
// Restructured:
//   stage 1: y_down[b,n,:] = lrelu(x_down[b,n,:] @ W_lin + b_lin)   (16384 rows/batch)
//   stage 2: out[b,m,:]    = lrelu(x_up[b,m,:] @ W_fus[0:128]
//                                  + y_down[b, idx[b,m], :] @ W_fus[128:256] + b_fus)
// Both stages are M x 256 x 128 GEMMs; stage 2's A-tile upper half is gathered.
// Inner product uses packed fma.rn.f32x2 (2 fp32 FMA/lane/inst) for 2x over FFMA.
// ---------------------------------------------------------------------------

constexpr int BATCH  = 4;
constexpr int N_DOWN = 16384;
constexpr int N_UP   = 65536;
constexpr float NSLOPE = 0.1f;

// Scratch for stage-1 output (33.5 MB). __device__ global = sanctioned scratch.
__device__ float g_ydown[(size_t)BATCH * N_DOWN * 128];
// Index dtype flag: 1 if up_idx buffer is int64, 0 if int32.
__device__ int g_idx_is64;

__device__ __forceinline__ unsigned long long ffma2(unsigned long long a,
                                                    unsigned long long b,
                                                    unsigned long long c) {
    unsigned long long d;
    asm("fma.rn.f32x2 %0, %1, %2, %3;" : "=l"(d) : "l"(a), "l"(b), "l"(c));
    return d;
}

__device__ __forceinline__ float2 unpack2(unsigned long long v) {
    float2 p;
    asm("mov.b64 {%0, %1}, %2;" : "=f"(p.x), "=f"(p.y) : "l"(v));
    return p;
}

__device__ __forceinline__ float lrelu(float x) { return x > 0.0f ? x : NSLOPE * x; }

// Detect whether the index buffer is int64 (odd 32-bit words all zero for values
// in [0,16384)) or int32. Deterministic for a given input. Safe: buffer holds
// >= 262144 32-bit words under either interpretation.
__global__ void detect_idx_kernel(const int* __restrict__ idx32) {
    int all0 = 1;
#pragma unroll
    for (int i = 1; i < 32; i += 2) all0 &= (idx32[i] == 0);
    g_idx_is64 = all0;
}

// GEMM: C[M,128] = lrelu(A[M,256] @ W[256,128] + bias)
// Tile: BM=128, BN=128, BK=16. 256 threads. Microtile 8m x 8n per thread,
// held as 4 (m,m+1) f32x2 pairs x 8 n. B is stored duplicated (b,b) in smem so
// the inner loop is pure LDS.128 + FFMA2.
template <int STAGE>
__global__ __launch_bounds__(256, 2)
void mlp_gemm(const float* __restrict__ A0,        // stage1: x_down[M,256]; stage2: x_up[M,128]
              const int* __restrict__ idx_raw,     // stage2 only
              const float* __restrict__ W,         // [256,128]
              const float* __restrict__ bias,      // [128]
              float* __restrict__ outp)            // stage2 output (stage1 -> g_ydown)
{
    __shared__ __align__(16) float  As[16][128];   // transposed A tile: As[k][m]
    __shared__ __align__(16) float2 Bs[16][128];   // duplicated W tile: (w,w)

    const int tid   = threadIdx.x;
    const int m_blk = blockIdx.x * 128;

    // ---- A-load role: row ar (0..127), col-halves of the 16-wide k chunk ----
    const int ar = tid >> 1;
    const int ah = (tid & 1) << 3;         // 0 or 8
    const int mg = m_blk + ar;             // global row

    const float* alo;
    const float* ahi;
    if (STAGE == 1) {
        alo = A0 + (size_t)mg * 256;
        ahi = alo + 128;
    } else {
        alo = A0 + (size_t)mg * 128;
        const int b = mg >> 16;            // mg / 65536
        int g;
        if (g_idx_is64) g = idx_raw[2 * mg];   // low word of int64
        else            g = idx_raw[mg];
        ahi = g_ydown + (size_t)(b * N_DOWN + g) * 128;
    }

    // ---- B-load role: row bk (0..15), cols bc..bc+7 ----
    const int bk = tid >> 4;
    const int bc = (tid & 15) << 3;

    // ---- compute role ----
    const int ty  = tid >> 4;              // 0..15 -> m0 = ty*8
    const int tx  = tid & 15;              // n pairs at 2*tx + 32*j
    const int cm0 = ty << 3;

    unsigned long long acc[4][8];
#pragma unroll
    for (int i = 0; i < 4; ++i)
#pragma unroll
        for (int j = 0; j < 8; ++j) acc[i][j] = 0ULL;

    for (int kc = 0; kc < 16; ++kc) {
        const int k0 = kc << 4;

        // global loads for this chunk
        const float* asrc = (k0 < 128 ? alo + k0 : ahi + (k0 - 128)) + ah;
        const float4 v0 = *(const float4*)asrc;
        const float4 v1 = *(const float4*)(asrc + 4);
        const float* wsrc = W + (k0 + bk) * 128 + bc;
        const float4 w0 = *(const float4*)wsrc;
        const float4 w1 = *(const float4*)(wsrc + 4);

        As[ah + 0][ar] = v0.x; As[ah + 1][ar] = v0.y;
        As[ah + 2][ar] = v0.z; As[ah + 3][ar] = v0.w;
        As[ah + 4][ar] = v1.x; As[ah + 5][ar] = v1.y;
        As[ah + 6][ar] = v1.z; As[ah + 7][ar] = v1.w;

        Bs[bk][bc + 0] = make_float2(w0.x, w0.x);
        Bs[bk][bc + 1] = make_float2(w0.y, w0.y);
        Bs[bk][bc + 2] = make_float2(w0.z, w0.z);
        Bs[bk][bc + 3] = make_float2(w0.w, w0.w);
        Bs[bk][bc + 4] = make_float2(w1.x, w1.x);
        Bs[bk][bc + 5] = make_float2(w1.y, w1.y);
        Bs[bk][bc + 6] = make_float2(w1.z, w1.z);
        Bs[bk][bc + 7] = make_float2(w1.w, w1.w);

        __syncthreads();

#pragma unroll
        for (int k = 0; k < 16; ++k) {
            const ulonglong2 a01 = *(const ulonglong2*)(&As[k][cm0]);
            const ulonglong2 a23 = *(const ulonglong2*)(&As[k][cm0 + 4]);
            const unsigned long long av[4] = {a01.x, a01.y, a23.x, a23.y};
#pragma unroll
            for (int j = 0; j < 4; ++j) {
                // lanes 0..15 hit 16B-stride addresses -> conflict-free LDS.128
                const ulonglong2 bp =
                    *(const ulonglong2*)(&Bs[k][(tx << 1) + (j << 5)]);
#pragma unroll
                for (int mp = 0; mp < 4; ++mp) {
                    acc[mp][2 * j]     = ffma2(av[mp], bp.x, acc[mp][2 * j]);
                    acc[mp][2 * j + 1] = ffma2(av[mp], bp.y, acc[mp][2 * j + 1]);
                }
            }
        }
        __syncthreads();
    }

    // ---- epilogue: bias + leaky relu, coalesced float2 stores ----
    float* dst = (STAGE == 1) ? g_ydown : outp;

    float bv0[4], bv1[4];
#pragma unroll
    for (int j = 0; j < 4; ++j) {
        const int n = (tx << 1) + (j << 5);
        bv0[j] = bias[n];
        bv1[j] = bias[n + 1];
    }

#pragma unroll
    for (int mp = 0; mp < 4; ++mp) {
        const int r0 = m_blk + cm0 + 2 * mp;
        float* row0 = dst + (size_t)r0 * 128;
        float* row1 = row0 + 128;
#pragma unroll
        for (int j = 0; j < 4; ++j) {
            const float2 pa = unpack2(acc[mp][2 * j]);      // .x -> row r0, .y -> r0+1
            const float2 pb = unpack2(acc[mp][2 * j + 1]);
            const int n = (tx << 1) + (j << 5);
            *(float2*)(row0 + n) = make_float2(lrelu(pa.x + bv0[j]), lrelu(pb.x + bv1[j]));
            *(float2*)(row1 + n) = make_float2(lrelu(pa.y + bv0[j]), lrelu(pb.y + bv1[j]));
        }
    }
}

extern "C" void kernel_launch(void* const* d_in, const int* in_sizes, int n_in,
                              void* d_out, int out_size) {
    const float* x_down = (const float*)d_in[0];
    const float* x_up   = (const float*)d_in[1];
    const int*   up_idx = (const int*)d_in[2];   // int32 or int64 (detected on device)
    const float* W_lin  = (const float*)d_in[3];
    const float* b_lin  = (const float*)d_in[4];
    const float* W_fus  = (const float*)d_in[5];
    const float* b_fus  = (const float*)d_in[6];
    float* out = (float*)d_out;

    detect_idx_kernel<<<1, 1>>>(up_idx);
    mlp_gemm<1><<<(BATCH * N_DOWN) / 128, 256>>>(x_down, nullptr, W_lin, b_lin, nullptr);
    mlp_gemm<2><<<(BATCH * N_UP) / 128, 256>>>(x_up, up_idx, W_fus, b_fus, out);
}

// round 4
// speedup vs baseline: 1.7892x; 1.7892x over previous
#include <cuda_runtime.h>
#include <cuda_bf16.h>

// ---------------------------------------------------------------------------
// Upsampling via two bf16 mma.sync GEMMs (HMMA path; tcgen05 unusable: the
// harness lowers through .target sm_103 which rejects all 'a'-gated features).
//   stage 1: y_down = lrelu(x_down @ W_lin + b_lin)       [65536 x 256 x 128]
//   stage 2: out = lrelu([x_up | gather(y_down)] @ W_fus + b_fus)
//                                                         [262144 x 256 x 128]
// fp32 emulation: x = hi + lo (bf16 each); D = Ahi*Bhi + Ahi*Blo + Alo*Bhi
// accumulated in fp32 registers. rel_err ~1.5e-5.
// ---------------------------------------------------------------------------

constexpr int BATCH = 4, N_DOWN = 16384, N_UP = 65536;
constexpr float NSLOPE = 0.1f;

__device__ float g_ydown[(size_t)BATCH * N_DOWN * 128];
__device__ int g_idx_is64;

// Pre-split, pre-transposed W^T images: per stage [hi | lo], each [128 n][264 k] bf16
constexpr int BSTR = 264;                    // bf16/row: 256 + 8 pad -> 528 B (16B-mult)
constexpr int BHSIZE = 128 * BSTR * 2;       // 67584 B
__device__ __align__(16) unsigned char g_Bt[2][2 * BHSIZE];

constexpr int ASTR = 72;                     // bf16/row: 64 + 8 pad -> 144 B
constexpr int AHSIZE = 128 * ASTR * 2;       // 18432 B

// smem layout (dynamic)
constexpr int SM_ROWPTR = 0;                 // 128 x 8B gather pointers (stage 2)
constexpr int SM_B = 1024;                   // 2*BHSIZE = 135168 (hi | lo)
constexpr int SM_A = SM_B + 2 * BHSIZE;      // 2*AHSIZE = 36864 (hi | lo)
constexpr int SM_TOTAL = SM_A + 2 * AHSIZE;  // 173056 B

__device__ __forceinline__ float lrelu(float x) { return x > 0.0f ? x : NSLOPE * x; }

__device__ __forceinline__ unsigned smem_u32(const void* p) {
    unsigned a;
    asm("{ .reg .u64 t; cvta.to.shared.u64 t, %1; cvt.u32.u64 %0, t; }" : "=r"(a) : "l"(p));
    return a;
}

#define LDSM4(r, a) asm volatile( \
    "ldmatrix.sync.aligned.m8n8.x4.shared.b16 {%0,%1,%2,%3}, [%4];" \
    : "=r"((r)[0]), "=r"((r)[1]), "=r"((r)[2]), "=r"((r)[3]) : "r"(a))
#define LDSM2(r, a) asm volatile( \
    "ldmatrix.sync.aligned.m8n8.x2.shared.b16 {%0,%1}, [%2];" \
    : "=r"((r)[0]), "=r"((r)[1]) : "r"(a))
#define MMA(d, a, b) asm volatile( \
    "mma.sync.aligned.m16n8k16.row.col.f32.bf16.bf16.f32 " \
    "{%0,%1,%2,%3}, {%4,%5,%6,%7}, {%8,%9}, {%0,%1,%2,%3};" \
    : "+f"((d)[0]), "+f"((d)[1]), "+f"((d)[2]), "+f"((d)[3]) \
    : "r"((a)[0]), "r"((a)[1]), "r"((a)[2]), "r"((a)[3]), "r"((b)[0]), "r"((b)[1]))

__device__ __forceinline__ void split2(float a, float b, unsigned& h, unsigned& l) {
    __nv_bfloat16 ha = __float2bfloat16(a), hb = __float2bfloat16(b);
    float ra = a - __bfloat162float(ha), rb = b - __bfloat162float(hb);
    __nv_bfloat16 la = __float2bfloat16(ra), lb = __float2bfloat16(rb);
    h = (unsigned)__bfloat16_as_ushort(ha) | ((unsigned)__bfloat16_as_ushort(hb) << 16);
    l = (unsigned)__bfloat16_as_ushort(la) | ((unsigned)__bfloat16_as_ushort(lb) << 16);
}

// ---- probe index dtype: int64 has odd 32-bit words == 0 for values < 16384 ----
__global__ void detect_idx_kernel(const int* __restrict__ idx32) {
    int all0 = 1;
#pragma unroll
    for (int i = 1; i < 32; i += 2) all0 &= (idx32[i] == 0);
    g_idx_is64 = all0;
}

// ---- pre-split + transpose W[k][n] -> BT[n][k] (padded), hi and lo images ----
__global__ void prep_w(const float* __restrict__ Wl, const float* __restrict__ Wf) {
    int idx = blockIdx.x * 256 + threadIdx.x;   // 0..65535
    int stage = idx >> 15;
    int rem = idx & 32767;
    int k = rem >> 7, n = rem & 127;
    const float* W = stage ? Wf : Wl;
    float w = W[k * 128 + n];
    __nv_bfloat16 h = __float2bfloat16(w);
    float r = w - __bfloat162float(h);
    __nv_bfloat16 l = __float2bfloat16(r);
    unsigned char* base = g_Bt[stage];
    int off = n * (BSTR * 2) + k * 2;
    *(unsigned short*)(base + off) = __bfloat16_as_ushort(h);
    *(unsigned short*)(base + BHSIZE + off) = __bfloat16_as_ushort(l);
}

template <int STAGE>
__global__ __launch_bounds__(512, 1)
void gemm_mma(const float* __restrict__ A0,      // s1: x_down[M,256]; s2: x_up[M,128]
              const int* __restrict__ idx_raw,   // s2 only
              const unsigned char* __restrict__ Bimg,
              const float* __restrict__ bias,
              float* __restrict__ outp) {
    extern __shared__ __align__(16) char s[];
    const unsigned sbase = smem_u32(s);
    const int tid = threadIdx.x;
    const int lane = tid & 31;
    const int w = tid >> 5;
    const int wm = w >> 2, wn = w & 3;           // 4x4 warp grid, 32m x 32n each
    const int m_blk = blockIdx.x * 128;

    // gather pointers (stage 2)
    if (STAGE == 2 && tid < 128) {
        const int mg = m_blk + tid;
        const int b = mg >> 16;
        int g;
        if (g_idx_is64) g = idx_raw[2 * mg]; else g = idx_raw[mg];
        ((const float**)(s + SM_ROWPTR))[tid] = g_ydown + (size_t)(b * N_DOWN + g) * 128;
    }
    // copy full B image (hi|lo, padded) into smem
    {
        const float4* src = (const float4*)Bimg;
        float4* dst = (float4*)(s + SM_B);
        for (int i = tid; i < (2 * BHSIZE) / 16; i += 512) dst[i] = src[i];
    }
    __syncthreads();

    // conversion role: row r (0..127), 16-float segment seg
    const int cr = tid >> 2;
    const int seg = (tid & 3) * 16;
    const int mg = m_blk + cr;
    const float* rowp = (STAGE == 2) ? ((const float**)(s + SM_ROWPTR))[cr] : nullptr;

    // per-lane ldmatrix base addresses
    const unsigned pA = sbase + SM_A + (wm * 32 + (lane & 15)) * 144 + (lane >> 4) * 16;
    const unsigned pB = sbase + SM_B + (wn * 32 + (lane & 7)) * 528 + ((lane >> 3) & 1) * 16;

    float d[2][4][4];
#pragma unroll
    for (int mf = 0; mf < 2; ++mf)
#pragma unroll
        for (int nf = 0; nf < 4; ++nf)
#pragma unroll
            for (int i = 0; i < 4; ++i) d[mf][nf][i] = 0.0f;

    for (int c = 0; c < 4; ++c) {
        // ---- convert A chunk [128 x 64] fp32 -> bf16 hi/lo into padded smem ----
        const float* src;
        if (STAGE == 1)       src = A0 + (size_t)mg * 256 + c * 64 + seg;
        else if (c < 2)       src = A0 + (size_t)mg * 128 + c * 64 + seg;
        else                  src = rowp + (c - 2) * 64 + seg;
        {
            char* ah = s + SM_A + cr * 144 + seg * 2;
            char* al = ah + AHSIZE;
            const float4 u0 = ((const float4*)src)[0];
            const float4 u1 = ((const float4*)src)[1];
            const float4 u2 = ((const float4*)src)[2];
            const float4 u3 = ((const float4*)src)[3];
            unsigned h0, h1, h2, h3, h4, h5, h6, h7, l0, l1, l2, l3, l4, l5, l6, l7;
            split2(u0.x, u0.y, h0, l0); split2(u0.z, u0.w, h1, l1);
            split2(u1.x, u1.y, h2, l2); split2(u1.z, u1.w, h3, l3);
            split2(u2.x, u2.y, h4, l4); split2(u2.z, u2.w, h5, l5);
            split2(u3.x, u3.y, h6, l6); split2(u3.z, u3.w, h7, l7);
            ((uint4*)ah)[0] = make_uint4(h0, h1, h2, h3);
            ((uint4*)ah)[1] = make_uint4(h4, h5, h6, h7);
            ((uint4*)al)[0] = make_uint4(l0, l1, l2, l3);
            ((uint4*)al)[1] = make_uint4(l4, l5, l6, l7);
        }
        __syncthreads();

        // ---- MMA over this 64-k chunk: 4 ksteps of 16 ----
#pragma unroll
        for (int ks = 0; ks < 4; ++ks) {
            unsigned aH[2][4], aL[2][4];
#pragma unroll
            for (int mf = 0; mf < 2; ++mf) {
                const unsigned pa = pA + mf * (16 * 144) + ks * 32;
                LDSM4(aH[mf], pa);
                LDSM4(aL[mf], pa + AHSIZE);
            }
            const unsigned kb = (c * 64 + ks * 16) * 2;
#pragma unroll
            for (int nf = 0; nf < 4; ++nf) {
                unsigned bH[2], bL[2];
                const unsigned pb = pB + nf * (8 * 528) + kb;
                LDSM2(bH, pb);
                LDSM2(bL, pb + BHSIZE);
#pragma unroll
                for (int mf = 0; mf < 2; ++mf) {
                    MMA(d[mf][nf], aH[mf], bH);
                    MMA(d[mf][nf], aH[mf], bL);
                    MMA(d[mf][nf], aL[mf], bH);
                }
            }
        }
        __syncthreads();   // before next chunk overwrites A smem
    }

    // ---- epilogue: bias + leaky relu, float2 register stores ----
    float* dst = (STAGE == 1) ? g_ydown : outp;
    const int col0 = wn * 32 + 2 * (lane & 3);
    const int row0 = m_blk + wm * 32 + (lane >> 2);

    float2 bb[4];
#pragma unroll
    for (int nf = 0; nf < 4; ++nf) bb[nf] = *(const float2*)(bias + col0 + nf * 8);

#pragma unroll
    for (int mf = 0; mf < 2; ++mf) {
        float* r0 = dst + (size_t)(row0 + mf * 16) * 128;
        float* r1 = r0 + 8 * 128;
#pragma unroll
        for (int nf = 0; nf < 4; ++nf) {
            const int cc = col0 + nf * 8;
            *(float2*)(r0 + cc) = make_float2(lrelu(d[mf][nf][0] + bb[nf].x),
                                              lrelu(d[mf][nf][1] + bb[nf].y));
            *(float2*)(r1 + cc) = make_float2(lrelu(d[mf][nf][2] + bb[nf].x),
                                              lrelu(d[mf][nf][3] + bb[nf].y));
        }
    }
}

extern "C" void kernel_launch(void* const* d_in, const int* in_sizes, int n_in,
                              void* d_out, int out_size) {
    const float* x_down = (const float*)d_in[0];
    const float* x_up   = (const float*)d_in[1];
    const int*   up_idx = (const int*)d_in[2];
    const float* W_lin  = (const float*)d_in[3];
    const float* b_lin  = (const float*)d_in[4];
    const float* W_fus  = (const float*)d_in[5];
    const float* b_fus  = (const float*)d_in[6];
    float* out = (float*)d_out;

    cudaFuncSetAttribute(gemm_mma<1>, cudaFuncAttributeMaxDynamicSharedMemorySize, SM_TOTAL);
    cudaFuncSetAttribute(gemm_mma<2>, cudaFuncAttributeMaxDynamicSharedMemorySize, SM_TOTAL);

    detect_idx_kernel<<<1, 1>>>(up_idx);
    prep_w<<<256, 256>>>(W_lin, W_fus);

    unsigned char* bimg0;
    cudaGetSymbolAddress((void**)&bimg0, g_Bt);
    unsigned char* bimg1 = bimg0 + 2 * BHSIZE;

    gemm_mma<1><<<(BATCH * N_DOWN) / 128, 512, SM_TOTAL>>>(x_down, nullptr, bimg0, b_lin, nullptr);
    gemm_mma<2><<<(BATCH * N_UP) / 128, 512, SM_TOTAL>>>(x_up, up_idx, bimg1, b_fus, out);
}